// round 6
// baseline (speedup 1.0000x reference)
#include <cuda_runtime.h>
#include <cstdint>

#define NMAX 50000
#define EMAX 800000

// Scratch (device globals; no allocation allowed)
__device__ __align__(256) float g_h[2][(size_t)NMAX * 64];
__device__ __align__(256) int   g_cnt[NMAX];
__device__ __align__(256) int   g_fill[NMAX];
__device__ __align__(256) int   g_rowptr[NMAX + 1];
__device__ __align__(256) int   g_csr_src[EMAX];
__device__ __align__(256) float g_t[NMAX];
__device__ int g_is64;

// ---------------- edge dtype detection ----------------
// int64 indices < 50000 => every odd 32-bit word is 0. int32 data => odd words
// are random src indices (64 zeros in a row is impossible in practice).
// Samples stay within the first E int32 words: in-bounds under BOTH hypotheses.
__global__ void detect_kernel(const int* ei32, int E) {
    int all0 = 1;
    for (int k = 0; k < 64; k++) {
        long long p = 1 + 2 * ((long long)k * (E / 2 - 1) / 64);
        if (ei32[p] != 0) { all0 = 0; break; }
    }
    g_is64 = all0;
}

__device__ __forceinline__ int load_idx(const void* ei, int E, int half, int e, int is64, int n) {
    int v;
    if (is64) v = (int)((const long long*)ei)[(size_t)half * E + e];
    else      v = ((const int*)ei)[(size_t)half * E + e];
    // defensive clamp: a wrong value shows up as rel_err, never as a fault
    return min(max(v, 0), n - 1);
}

// ---------------- CSR build ----------------

__global__ void zero_start(int n) {
    int i = blockIdx.x * blockDim.x + threadIdx.x;
    int stride = gridDim.x * blockDim.x;
    for (int j = i; j < n; j += stride) { g_cnt[j] = 0; g_fill[j] = 0; }
}

__global__ void count_kernel(const void* __restrict__ ei, int E, int n) {
    int e = blockIdx.x * blockDim.x + threadIdx.x;
    if (e >= E) return;
    int is64 = g_is64;
    int d = load_idx(ei, E, 1, e, is64, n);
    atomicAdd(&g_cnt[d], 1);
}

// Single-block exclusive scan over g_cnt -> g_rowptr
__global__ void scan_kernel(int n) {
    __shared__ int sums[1024];
    int t = threadIdx.x;
    int chunk = (n + 1023) / 1024;
    int beg = t * chunk;
    int endi = min(beg + chunk, n);
    int s = 0;
    for (int i = beg; i < endi; i++) s += g_cnt[i];
    sums[t] = s;
    __syncthreads();
    for (int off = 1; off < 1024; off <<= 1) {
        int v = sums[t];
        int u = (t >= off) ? sums[t - off] : 0;
        __syncthreads();
        sums[t] = v + u;
        __syncthreads();
    }
    int excl = (t == 0) ? 0 : sums[t - 1];
    for (int i = beg; i < endi; i++) {
        g_rowptr[i] = excl;
        excl += g_cnt[i];
    }
    if (t == 0) g_rowptr[n] = sums[1023];
}

__global__ void fill_kernel(const void* __restrict__ ei, int E, int n) {
    int e = blockIdx.x * blockDim.x + threadIdx.x;
    if (e >= E) return;
    int is64 = g_is64;
    int s = load_idx(ei, E, 0, e, is64, n);
    int d = load_idx(ei, E, 1, e, is64, n);
    int pos = g_rowptr[d] + atomicAdd(&g_fill[d], 1);
    if (pos < EMAX) g_csr_src[pos] = s;
}

// ---------------- Fused layer: CIN=64 ----------------
// Block: 256 threads (8 warps), 16 rows/block (2 nodes per warp).
// Phase 1: warp-per-node CSR gather (mean agg) + own h row -> shared
// Phase 2: GEMM  out = relu([agg|h] @ [Wl;Wr] + bl), 1 row x 4 cols per thread
// FT: fuse t = out @ Wl4 (scalar per node) via 16-lane butterfly.
template <bool FT>
__global__ void __launch_bounds__(256) fused64(
    int in_idx, int out_idx,
    const float* __restrict__ Wl, const float* __restrict__ bl,
    const float* __restrict__ Wr, const float* __restrict__ Wl4,
    int n)
{
    constexpr int ROWS = 16;
    constexpr int L = 132;  // agg [0..63], pad, h [66..129]
    __shared__ __align__(16) float w_s[2 * 64 * 64];   // 32 KB
    __shared__ __align__(16) float in_s[ROWS * L];     // 8.25 KB
    __shared__ float bl_s[64];
    __shared__ float wl4_s[64];

    const float* hin = g_h[in_idx];
    float* hout = g_h[out_idx];

    int tid = threadIdx.x;
    int base = blockIdx.x * ROWS;
    int warp = tid >> 5;
    int lane = tid & 31;

    for (int i = tid; i < 64 * 64; i += 256) {
        w_s[i] = Wl[i];
        w_s[64 * 64 + i] = Wr[i];
    }
    if (tid < 64) {
        bl_s[tid] = bl[tid];
        if (FT) wl4_s[tid] = Wl4[tid];
    }

    // Phase 1: gather (warp-uniform control per row)
#pragma unroll
    for (int q = 0; q < 2; q++) {
        int r = warp * 2 + q;
        int row = base + r;
        float2 acc = make_float2(0.f, 0.f);
        if (row < n) {
            int start = g_rowptr[row];
            int end = g_rowptr[row + 1];
            for (int j = start; j < end; j += 32) {
                int m = min(32, end - j);
                int eid = (lane < m) ? g_csr_src[j + lane] : 0;
#pragma unroll
                for (int k = 0; k < 32; k += 8) {
                    if (k >= m) break;
                    float2 v[8];
#pragma unroll
                    for (int u = 0; u < 8; u++) {
                        int s = __shfl_sync(0xffffffffu, eid, k + u);
                        if (k + u < m)
                            v[u] = *(const float2*)(hin + (size_t)s * 64 + 2 * lane);
                        else
                            v[u] = make_float2(0.f, 0.f);
                    }
#pragma unroll
                    for (int u = 0; u < 8; u++) { acc.x += v[u].x; acc.y += v[u].y; }
                }
            }
            int deg = end - start;
            float inv = 1.0f / (float)max(deg, 1);
            acc.x *= inv; acc.y *= inv;
            float2 hv = *(const float2*)(hin + (size_t)row * 64 + 2 * lane);
            *(float2*)&in_s[r * L + 66 + 2 * lane] = hv;
        }
        *(float2*)&in_s[r * L + 2 * lane] = acc;
    }
    __syncthreads();

    // Phase 2: GEMM. thread -> (rr, cg): row rr, cols [cg*4, cg*4+4)
    int rr = tid >> 4;
    int cg = tid & 15;
    int j0 = cg * 4;
    const float4* w4 = (const float4*)w_s;

    float a0[4];
#pragma unroll
    for (int c = 0; c < 4; c++) a0[c] = bl_s[j0 + c];

    const float* r0p = &in_s[rr * L];
#pragma unroll
    for (int k = 0; k < 64; k++) {
        float4 w = w4[k * 16 + cg];
        float x0 = r0p[k];
        a0[0] += x0 * w.x; a0[1] += x0 * w.y; a0[2] += x0 * w.z; a0[3] += x0 * w.w;
    }
#pragma unroll
    for (int k = 0; k < 64; k++) {
        float4 w = w4[(64 + k) * 16 + cg];
        float x0 = r0p[66 + k];
        a0[0] += x0 * w.x; a0[1] += x0 * w.y; a0[2] += x0 * w.z; a0[3] += x0 * w.w;
    }
#pragma unroll
    for (int c = 0; c < 4; c++) a0[c] = fmaxf(a0[c], 0.f);

    int row0 = base + rr;
    if (row0 < n) *(float4*)(hout + (size_t)row0 * 64 + j0) = make_float4(a0[0], a0[1], a0[2], a0[3]);

    if (FT) {
        float p0 = a0[0] * wl4_s[j0] + a0[1] * wl4_s[j0 + 1] + a0[2] * wl4_s[j0 + 2] + a0[3] * wl4_s[j0 + 3];
#pragma unroll
        for (int off = 8; off >= 1; off >>= 1)
            p0 += __shfl_xor_sync(0xffffffffu, p0, off);
        if (cg == 0 && row0 < n) g_t[row0] = p0;
    }
}

// ---------------- Fused layer 0: CIN=13 ----------------
__global__ void __launch_bounds__(256) fused13(
    const float* __restrict__ x,
    const float* __restrict__ Wl, const float* __restrict__ bl,
    const float* __restrict__ Wr, int n)
{
    constexpr int ROWS = 32;
    constexpr int L = 28;  // agg [0..12], pad, h [14..26]
    __shared__ __align__(16) float w_s[2 * 13 * 64];
    __shared__ __align__(16) float in_s[ROWS * L];
    __shared__ float bl_s[64];

    float* hout = g_h[0];
    int tid = threadIdx.x;
    int base = blockIdx.x * ROWS;
    int warp = tid >> 5;
    int lane = tid & 31;

    for (int i = tid; i < 2 * 13 * 64; i += 256) w_s[i] = (i < 13 * 64) ? Wl[i] : Wr[i - 13 * 64];
    if (tid < 64) bl_s[tid] = bl[tid];

    for (int q = 0; q < 4; q++) {
        int r = warp * 4 + q;
        int row = base + r;
        float acc = 0.f;
        if (row < n) {
            int start = g_rowptr[row];
            int end = g_rowptr[row + 1];
            for (int j = start; j < end; j += 32) {
                int m = min(32, end - j);
                int eid = (lane < m) ? g_csr_src[j + lane] : 0;
#pragma unroll
                for (int k = 0; k < 32; k += 8) {
                    if (k >= m) break;
                    float v[8];
#pragma unroll
                    for (int u = 0; u < 8; u++) {
                        int s = __shfl_sync(0xffffffffu, eid, k + u);
                        v[u] = (lane < 13 && k + u < m) ? __ldg(&x[(size_t)s * 13 + lane]) : 0.f;
                    }
#pragma unroll
                    for (int u = 0; u < 8; u++) acc += v[u];
                }
            }
            int deg = end - start;
            float inv = 1.0f / (float)max(deg, 1);
            if (lane < 13) {
                in_s[r * L + lane] = acc * inv;
                in_s[r * L + 14 + lane] = __ldg(&x[(size_t)row * 13 + lane]);
            }
        } else if (lane < 13) {
            in_s[r * L + lane] = 0.f;
            in_s[r * L + 14 + lane] = 0.f;
        }
    }
    __syncthreads();

    int rr = tid >> 4;
    int cg = tid & 15;
    int j0 = cg * 4;
    const float4* w4 = (const float4*)w_s;

    float a0[4], a1[4];
#pragma unroll
    for (int c = 0; c < 4; c++) { a0[c] = bl_s[j0 + c]; a1[c] = bl_s[j0 + c]; }

    const float* r0p = &in_s[rr * L];
    const float* r1p = &in_s[(rr + 16) * L];
#pragma unroll
    for (int k = 0; k < 13; k++) {
        float4 w = w4[k * 16 + cg];
        float x0 = r0p[k], x1 = r1p[k];
        a0[0] += x0 * w.x; a0[1] += x0 * w.y; a0[2] += x0 * w.z; a0[3] += x0 * w.w;
        a1[0] += x1 * w.x; a1[1] += x1 * w.y; a1[2] += x1 * w.z; a1[3] += x1 * w.w;
    }
#pragma unroll
    for (int k = 0; k < 13; k++) {
        float4 w = w4[(13 + k) * 16 + cg];
        float x0 = r0p[14 + k], x1 = r1p[14 + k];
        a0[0] += x0 * w.x; a0[1] += x0 * w.y; a0[2] += x0 * w.z; a0[3] += x0 * w.w;
        a1[0] += x1 * w.x; a1[1] += x1 * w.y; a1[2] += x1 * w.z; a1[3] += x1 * w.w;
    }

    int row0 = base + rr;
    int row1 = base + rr + 16;
    if (row0 < n) {
#pragma unroll
        for (int c = 0; c < 4; c++) a0[c] = fmaxf(a0[c], 0.f);
        *(float4*)(hout + (size_t)row0 * 64 + j0) = make_float4(a0[0], a0[1], a0[2], a0[3]);
    }
    if (row1 < n) {
#pragma unroll
        for (int c = 0; c < 4; c++) a1[c] = fmaxf(a1[c], 0.f);
        *(float4*)(hout + (size_t)row1 * 64 + j0) = make_float4(a1[0], a1[1], a1[2], a1[3]);
    }
}

// ---------------- Final layer (64 -> 1), gather of precomputed t ----------------
__global__ void __launch_bounds__(256) final_kernel(
    int in_idx,
    const float* __restrict__ Wr,
    const float* __restrict__ bl,
    float* __restrict__ out, int n)
{
    __shared__ float w[64];
    if (threadIdx.x < 64) w[threadIdx.x] = Wr[threadIdx.x];
    __syncthreads();
    const float* h = g_h[in_idx];

    int gw = (blockIdx.x * blockDim.x + threadIdx.x) >> 5;
    if (gw >= n) return;
    int lane = threadIdx.x & 31;

    int start = g_rowptr[gw];
    int end = g_rowptr[gw + 1];
    float sum = 0.f;
    for (int j = start + lane; j < end; j += 32) sum += __ldg(&g_t[g_csr_src[j]]);

    float inv = 1.0f / (float)max(end - start, 1);
    float2 hv = *(const float2*)(h + (size_t)gw * 64 + 2 * lane);
    float2 wv = *(const float2*)&w[2 * lane];
    float v = sum * inv + hv.x * wv.x + hv.y * wv.y;
#pragma unroll
    for (int off = 16; off >= 1; off >>= 1) v += __shfl_xor_sync(0xffffffffu, v, off);

    if (lane == 0) {
        float z = v + bl[0];
        out[gw] = 1.0f / (1.0f + __expf(-z));
    }
}

// ---------------- launch ----------------
extern "C" void kernel_launch(void* const* d_in, const int* in_sizes, int n_in,
                              void* d_out, int out_size) {
    const float* x = (const float*)d_in[0];
    const void* ei = d_in[1];
    const float* Wl[5]; const float* bl[5]; const float* Wr[5];
    for (int i = 0; i < 5; i++) {
        Wl[i] = (const float*)d_in[2 + 3 * i];
        bl[i] = (const float*)d_in[3 + 3 * i];
        Wr[i] = (const float*)d_in[4 + 3 * i];
    }
    int n = in_sizes[0] / 13;
    int E = in_sizes[1] / 2;
    float* out = (float*)d_out;

    int eb = (E + 255) / 256;
    int fb13 = (n + 31) / 32;
    int fb64 = (n + 15) / 16;

    detect_kernel<<<1, 1>>>((const int*)ei, E);
    zero_start<<<64, 256>>>(n);
    count_kernel<<<eb, 256>>>(ei, E, n);
    scan_kernel<<<1, 1024>>>(n);
    fill_kernel<<<eb, 256>>>(ei, E, n);

    fused13<<<fb13, 256>>>(x, Wl[0], bl[0], Wr[0], n);                      // -> g_h[0]
    fused64<false><<<fb64, 256>>>(0, 1, Wl[1], bl[1], Wr[1], Wl[1], n);     // h0 -> h1
    fused64<false><<<fb64, 256>>>(1, 0, Wl[2], bl[2], Wr[2], Wl[2], n);     // h1 -> h0
    fused64<true><<<fb64, 256>>>(0, 1, Wl[3], bl[3], Wr[3], Wl[4], n);      // h0 -> h1, t = h3 @ Wl4
    final_kernel<<<(n * 32 + 255) / 256, 256>>>(1, Wr[4], bl[4], out, n);
}

// round 7
// speedup vs baseline: 1.4542x; 1.4542x over previous
#include <cuda_runtime.h>
#include <cstdint>

#define NMAX 50000
#define EMAX 800000

// Scratch (device globals; no allocation allowed)
__device__ __align__(256) float g_h[2][(size_t)NMAX * 64];
__device__ __align__(256) int   g_cnt[NMAX];
__device__ __align__(256) int   g_fill[NMAX];
__device__ __align__(256) int   g_rowptr[NMAX + 1];
__device__ __align__(256) int   g_csr_src[EMAX];
__device__ __align__(256) float g_t[NMAX];
__device__ __align__(256) int   g_bsum[256];
__device__ __align__(256) int   g_bscan[256];
__device__ int g_is64;

// ---------------- zero + edge dtype detection (fused) ----------------
// int64 indices < 50000 => every odd 32-bit word is 0. int32 data => odd words
// are random src indices (64 zeros in a row is impossible in practice).
__global__ void zero_start(const int* ei32, int E, int n) {
    int i = blockIdx.x * blockDim.x + threadIdx.x;
    int stride = gridDim.x * blockDim.x;
    for (int j = i; j < n; j += stride) { g_cnt[j] = 0; g_fill[j] = 0; }
    if (i == 0) {
        int all0 = 1;
        for (int k = 0; k < 64; k++) {
            long long p = 1 + 2 * ((long long)k * (E / 2 - 1) / 64);
            if (ei32[p] != 0) { all0 = 0; break; }
        }
        g_is64 = all0;
    }
}

__device__ __forceinline__ int load_idx(const void* ei, int E, int half, int e, int is64, int n) {
    int v;
    if (is64) v = (int)((const long long*)ei)[(size_t)half * E + e];
    else      v = ((const int*)ei)[(size_t)half * E + e];
    return min(max(v, 0), n - 1);  // defensive clamp
}

__global__ void count_kernel(const void* __restrict__ ei, int E, int n) {
    int e = blockIdx.x * blockDim.x + threadIdx.x;
    if (e >= E) return;
    int is64 = g_is64;
    int d = load_idx(ei, E, 1, e, is64, n);
    atomicAdd(&g_cnt[d], 1);
}

// ---------------- 3-phase parallel exclusive scan ----------------
// Phase A: per-block (256 elems) partial sums
__global__ void __launch_bounds__(256) scan_partial(int n) {
    int t = threadIdx.x;
    int i = blockIdx.x * 256 + t;
    int v = (i < n) ? g_cnt[i] : 0;
    int w = v;
#pragma unroll
    for (int off = 16; off >= 1; off >>= 1) w += __shfl_xor_sync(0xffffffffu, w, off);
    __shared__ int red[8];
    if ((t & 31) == 0) red[t >> 5] = w;
    __syncthreads();
    if (t == 0) {
        int s = 0;
#pragma unroll
        for (int k = 0; k < 8; k++) s += red[k];
        g_bsum[blockIdx.x] = s;
    }
}

// Phase B: 1 block scans the <=256 block sums (exclusive), writes total to rowptr[n]
__global__ void __launch_bounds__(256) scan_bsum(int nb, int n) {
    __shared__ int s[256];
    int t = threadIdx.x;
    int v = (t < nb) ? g_bsum[t] : 0;
    s[t] = v;
    __syncthreads();
#pragma unroll
    for (int off = 1; off < 256; off <<= 1) {
        int a = s[t];
        int b = (t >= off) ? s[t - off] : 0;
        __syncthreads();
        s[t] = a + b;
        __syncthreads();
    }
    if (t < nb) g_bscan[t] = s[t] - v;   // exclusive
    if (t == nb - 1) g_rowptr[n] = s[t]; // total
}

// Phase C: block-local exclusive scan + block offset -> rowptr
__global__ void __launch_bounds__(256) scan_final(int n) {
    int t = threadIdx.x;
    int lane = t & 31;
    int wid = t >> 5;
    int i = blockIdx.x * 256 + t;
    int v = (i < n) ? g_cnt[i] : 0;
    // warp inclusive scan
    int inc = v;
#pragma unroll
    for (int off = 1; off < 32; off <<= 1) {
        int u = __shfl_up_sync(0xffffffffu, inc, off);
        if (lane >= off) inc += u;
    }
    __shared__ int wsum[8];
    if (lane == 31) wsum[wid] = inc;
    __syncthreads();
    if (t == 0) {
        int s = 0;
#pragma unroll
        for (int k = 0; k < 8; k++) { int u = wsum[k]; wsum[k] = s; s += u; }
    }
    __syncthreads();
    if (i < n) g_rowptr[i] = g_bscan[blockIdx.x] + wsum[wid] + inc - v;
}

__global__ void fill_kernel(const void* __restrict__ ei, int E, int n) {
    int e = blockIdx.x * blockDim.x + threadIdx.x;
    if (e >= E) return;
    int is64 = g_is64;
    int s = load_idx(ei, E, 0, e, is64, n);
    int d = load_idx(ei, E, 1, e, is64, n);
    int pos = g_rowptr[d] + atomicAdd(&g_fill[d], 1);
    if (pos < EMAX) g_csr_src[pos] = s;
}

// ---------------- Fused layer: CIN=64 (dynamic smem, ROWS=32) ----------------
// Block: 256 threads (8 warps), 32 rows/block (4 nodes per warp).
// Phase 1: warp-per-node CSR gather (mean agg) + own h row -> shared
// Phase 2: GEMM  out = relu([agg|h] @ [Wl;Wr] + bl), 2 rows x 4 cols per thread
// FT: fuse t = out @ Wl4 (scalar per node) via 16-lane butterfly.
#define F64_ROWS 32
#define F64_L 132
#define F64_DSMEM (2 * 64 * 64 * 4 + F64_ROWS * F64_L * 4 + 64 * 4 + 64 * 4)

template <bool FT>
__global__ void __launch_bounds__(256) fused64(
    int in_idx, int out_idx,
    const float* __restrict__ Wl, const float* __restrict__ bl,
    const float* __restrict__ Wr, const float* __restrict__ Wl4,
    int n)
{
    extern __shared__ __align__(16) float dyn[];
    float* w_s   = dyn;                         // 2*64*64
    float* in_s  = w_s + 2 * 64 * 64;           // ROWS * L
    float* bl_s  = in_s + F64_ROWS * F64_L;     // 64
    float* wl4_s = bl_s + 64;                   // 64

    const float* hin = g_h[in_idx];
    float* hout = g_h[out_idx];

    int tid = threadIdx.x;
    int base = blockIdx.x * F64_ROWS;
    int warp = tid >> 5;
    int lane = tid & 31;

    for (int i = tid; i < 64 * 64; i += 256) {
        w_s[i] = Wl[i];
        w_s[64 * 64 + i] = Wr[i];
    }
    if (tid < 64) {
        bl_s[tid] = bl[tid];
        if (FT) wl4_s[tid] = Wl4[tid];
    }

    // Phase 1: gather (warp-uniform control per row)
#pragma unroll
    for (int q = 0; q < 4; q++) {
        int r = warp * 4 + q;
        int row = base + r;
        float2 acc = make_float2(0.f, 0.f);
        if (row < n) {
            int start = g_rowptr[row];
            int end = g_rowptr[row + 1];
            for (int j = start; j < end; j += 32) {
                int m = min(32, end - j);
                int eid = (lane < m) ? g_csr_src[j + lane] : 0;
#pragma unroll
                for (int k = 0; k < 32; k += 8) {
                    if (k >= m) break;
                    float2 v[8];
#pragma unroll
                    for (int u = 0; u < 8; u++) {
                        int s = __shfl_sync(0xffffffffu, eid, k + u);
                        if (k + u < m)
                            v[u] = *(const float2*)(hin + (size_t)s * 64 + 2 * lane);
                        else
                            v[u] = make_float2(0.f, 0.f);
                    }
#pragma unroll
                    for (int u = 0; u < 8; u++) { acc.x += v[u].x; acc.y += v[u].y; }
                }
            }
            int deg = end - start;
            float inv = 1.0f / (float)max(deg, 1);
            acc.x *= inv; acc.y *= inv;
            float2 hv = *(const float2*)(hin + (size_t)row * 64 + 2 * lane);
            *(float2*)&in_s[r * F64_L + 66 + 2 * lane] = hv;
        }
        *(float2*)&in_s[r * F64_L + 2 * lane] = acc;
    }
    __syncthreads();

    // Phase 2: GEMM. thread -> (rr, cg): rows rr & rr+16, cols [cg*4, cg*4+4)
    int rr = tid >> 4;
    int cg = tid & 15;
    int j0 = cg * 4;
    const float4* w4 = (const float4*)w_s;

    float a0[4], a1[4];
#pragma unroll
    for (int c = 0; c < 4; c++) { a0[c] = bl_s[j0 + c]; a1[c] = bl_s[j0 + c]; }

    const float* r0p = &in_s[rr * F64_L];
    const float* r1p = &in_s[(rr + 16) * F64_L];
#pragma unroll
    for (int k = 0; k < 64; k++) {
        float4 w = w4[k * 16 + cg];
        float x0 = r0p[k], x1 = r1p[k];
        a0[0] += x0 * w.x; a0[1] += x0 * w.y; a0[2] += x0 * w.z; a0[3] += x0 * w.w;
        a1[0] += x1 * w.x; a1[1] += x1 * w.y; a1[2] += x1 * w.z; a1[3] += x1 * w.w;
    }
#pragma unroll
    for (int k = 0; k < 64; k++) {
        float4 w = w4[(64 + k) * 16 + cg];
        float x0 = r0p[66 + k], x1 = r1p[66 + k];
        a0[0] += x0 * w.x; a0[1] += x0 * w.y; a0[2] += x0 * w.z; a0[3] += x0 * w.w;
        a1[0] += x1 * w.x; a1[1] += x1 * w.y; a1[2] += x1 * w.z; a1[3] += x1 * w.w;
    }
#pragma unroll
    for (int c = 0; c < 4; c++) { a0[c] = fmaxf(a0[c], 0.f); a1[c] = fmaxf(a1[c], 0.f); }

    int row0 = base + rr;
    int row1 = base + rr + 16;
    if (row0 < n) *(float4*)(hout + (size_t)row0 * 64 + j0) = make_float4(a0[0], a0[1], a0[2], a0[3]);
    if (row1 < n) *(float4*)(hout + (size_t)row1 * 64 + j0) = make_float4(a1[0], a1[1], a1[2], a1[3]);

    if (FT) {
        float p0 = a0[0] * wl4_s[j0] + a0[1] * wl4_s[j0 + 1] + a0[2] * wl4_s[j0 + 2] + a0[3] * wl4_s[j0 + 3];
        float p1 = a1[0] * wl4_s[j0] + a1[1] * wl4_s[j0 + 1] + a1[2] * wl4_s[j0 + 2] + a1[3] * wl4_s[j0 + 3];
#pragma unroll
        for (int off = 8; off >= 1; off >>= 1) {
            p0 += __shfl_xor_sync(0xffffffffu, p0, off);
            p1 += __shfl_xor_sync(0xffffffffu, p1, off);
        }
        if (cg == 0) {
            if (row0 < n) g_t[row0] = p0;
            if (row1 < n) g_t[row1] = p1;
        }
    }
}

// ---------------- Fused layer 0: CIN=13 ----------------
__global__ void __launch_bounds__(256) fused13(
    const float* __restrict__ x,
    const float* __restrict__ Wl, const float* __restrict__ bl,
    const float* __restrict__ Wr, int n)
{
    constexpr int ROWS = 32;
    constexpr int L = 28;  // agg [0..12], pad, h [14..26]
    __shared__ __align__(16) float w_s[2 * 13 * 64];
    __shared__ __align__(16) float in_s[ROWS * L];
    __shared__ float bl_s[64];

    float* hout = g_h[0];
    int tid = threadIdx.x;
    int base = blockIdx.x * ROWS;
    int warp = tid >> 5;
    int lane = tid & 31;

    for (int i = tid; i < 2 * 13 * 64; i += 256) w_s[i] = (i < 13 * 64) ? Wl[i] : Wr[i - 13 * 64];
    if (tid < 64) bl_s[tid] = bl[tid];

    for (int q = 0; q < 4; q++) {
        int r = warp * 4 + q;
        int row = base + r;
        float acc = 0.f;
        if (row < n) {
            int start = g_rowptr[row];
            int end = g_rowptr[row + 1];
            for (int j = start; j < end; j += 32) {
                int m = min(32, end - j);
                int eid = (lane < m) ? g_csr_src[j + lane] : 0;
#pragma unroll
                for (int k = 0; k < 32; k += 8) {
                    if (k >= m) break;
                    float v[8];
#pragma unroll
                    for (int u = 0; u < 8; u++) {
                        int s = __shfl_sync(0xffffffffu, eid, k + u);
                        v[u] = (lane < 13 && k + u < m) ? __ldg(&x[(size_t)s * 13 + lane]) : 0.f;
                    }
#pragma unroll
                    for (int u = 0; u < 8; u++) acc += v[u];
                }
            }
            int deg = end - start;
            float inv = 1.0f / (float)max(deg, 1);
            if (lane < 13) {
                in_s[r * L + lane] = acc * inv;
                in_s[r * L + 14 + lane] = __ldg(&x[(size_t)row * 13 + lane]);
            }
        } else if (lane < 13) {
            in_s[r * L + lane] = 0.f;
            in_s[r * L + 14 + lane] = 0.f;
        }
    }
    __syncthreads();

    int rr = tid >> 4;
    int cg = tid & 15;
    int j0 = cg * 4;
    const float4* w4 = (const float4*)w_s;

    float a0[4], a1[4];
#pragma unroll
    for (int c = 0; c < 4; c++) { a0[c] = bl_s[j0 + c]; a1[c] = bl_s[j0 + c]; }

    const float* r0p = &in_s[rr * L];
    const float* r1p = &in_s[(rr + 16) * L];
#pragma unroll
    for (int k = 0; k < 13; k++) {
        float4 w = w4[k * 16 + cg];
        float x0 = r0p[k], x1 = r1p[k];
        a0[0] += x0 * w.x; a0[1] += x0 * w.y; a0[2] += x0 * w.z; a0[3] += x0 * w.w;
        a1[0] += x1 * w.x; a1[1] += x1 * w.y; a1[2] += x1 * w.z; a1[3] += x1 * w.w;
    }
#pragma unroll
    for (int k = 0; k < 13; k++) {
        float4 w = w4[(13 + k) * 16 + cg];
        float x0 = r0p[14 + k], x1 = r1p[14 + k];
        a0[0] += x0 * w.x; a0[1] += x0 * w.y; a0[2] += x0 * w.z; a0[3] += x0 * w.w;
        a1[0] += x1 * w.x; a1[1] += x1 * w.y; a1[2] += x1 * w.z; a1[3] += x1 * w.w;
    }

    int row0 = base + rr;
    int row1 = base + rr + 16;
    if (row0 < n) {
#pragma unroll
        for (int c = 0; c < 4; c++) a0[c] = fmaxf(a0[c], 0.f);
        *(float4*)(hout + (size_t)row0 * 64 + j0) = make_float4(a0[0], a0[1], a0[2], a0[3]);
    }
    if (row1 < n) {
#pragma unroll
        for (int c = 0; c < 4; c++) a1[c] = fmaxf(a1[c], 0.f);
        *(float4*)(hout + (size_t)row1 * 64 + j0) = make_float4(a1[0], a1[1], a1[2], a1[3]);
    }
}

// ---------------- Final layer (64 -> 1), gather of precomputed t ----------------
__global__ void __launch_bounds__(256) final_kernel(
    int in_idx,
    const float* __restrict__ Wr,
    const float* __restrict__ bl,
    float* __restrict__ out, int n)
{
    __shared__ float w[64];
    if (threadIdx.x < 64) w[threadIdx.x] = Wr[threadIdx.x];
    __syncthreads();
    const float* h = g_h[in_idx];

    int gw = (blockIdx.x * blockDim.x + threadIdx.x) >> 5;
    if (gw >= n) return;
    int lane = threadIdx.x & 31;

    int start = g_rowptr[gw];
    int end = g_rowptr[gw + 1];
    float sum = 0.f;
    for (int j = start + lane; j < end; j += 32) sum += __ldg(&g_t[g_csr_src[j]]);

    float inv = 1.0f / (float)max(end - start, 1);
    float2 hv = *(const float2*)(h + (size_t)gw * 64 + 2 * lane);
    float2 wv = *(const float2*)&w[2 * lane];
    float v = sum * inv + hv.x * wv.x + hv.y * wv.y;
#pragma unroll
    for (int off = 16; off >= 1; off >>= 1) v += __shfl_xor_sync(0xffffffffu, v, off);

    if (lane == 0) {
        float z = v + bl[0];
        out[gw] = 1.0f / (1.0f + __expf(-z));
    }
}

// ---------------- launch ----------------
extern "C" void kernel_launch(void* const* d_in, const int* in_sizes, int n_in,
                              void* d_out, int out_size) {
    const float* x = (const float*)d_in[0];
    const void* ei = d_in[1];
    const float* Wl[5]; const float* bl[5]; const float* Wr[5];
    for (int i = 0; i < 5; i++) {
        Wl[i] = (const float*)d_in[2 + 3 * i];
        bl[i] = (const float*)d_in[3 + 3 * i];
        Wr[i] = (const float*)d_in[4 + 3 * i];
    }
    int n = in_sizes[0] / 13;
    int E = in_sizes[1] / 2;
    float* out = (float*)d_out;

    int eb = (E + 255) / 256;
    int nb = (n + 255) / 256;          // scan blocks (<=256 assumed: n<=65536)
    int fb13 = (n + 31) / 32;
    int fb64 = (n + 31) / 32;

    cudaFuncSetAttribute(fused64<false>, cudaFuncAttributeMaxDynamicSharedMemorySize, F64_DSMEM);
    cudaFuncSetAttribute(fused64<true>,  cudaFuncAttributeMaxDynamicSharedMemorySize, F64_DSMEM);

    zero_start<<<64, 256>>>((const int*)ei, E, n);
    count_kernel<<<eb, 256>>>(ei, E, n);
    scan_partial<<<nb, 256>>>(n);
    scan_bsum<<<1, 256>>>(nb, n);
    scan_final<<<nb, 256>>>(n);
    fill_kernel<<<eb, 256>>>(ei, E, n);

    fused13<<<fb13, 256>>>(x, Wl[0], bl[0], Wr[0], n);                                  // -> g_h[0]
    fused64<false><<<fb64, 256, F64_DSMEM>>>(0, 1, Wl[1], bl[1], Wr[1], Wl[1], n);      // h0 -> h1
    fused64<false><<<fb64, 256, F64_DSMEM>>>(1, 0, Wl[2], bl[2], Wr[2], Wl[2], n);      // h1 -> h0
    fused64<true><<<fb64, 256, F64_DSMEM>>>(0, 1, Wl[3], bl[3], Wr[3], Wl[4], n);       // h0 -> h1, t = h3 @ Wl4
    final_kernel<<<(n * 32 + 255) / 256, 256>>>(1, Wr[4], bl[4], out, n);
}

// round 9
// speedup vs baseline: 1.5353x; 1.0557x over previous
#include <cuda_runtime.h>
#include <cstdint>

#define NMAX 50000
#define EMAX 800000

// Scratch (device globals; no allocation allowed)
__device__ __align__(256) float g_h[2][(size_t)NMAX * 64];
__device__ __align__(256) int   g_cnt[NMAX];
__device__ __align__(256) int   g_fill[NMAX];
__device__ __align__(256) int   g_rowptr[NMAX + 1];
__device__ __align__(256) int   g_csr_src[EMAX];
__device__ __align__(256) float g_t[NMAX];
__device__ __align__(256) int   g_bsum[256];
__device__ __align__(256) int   g_bscan[256];
__device__ int g_is64;

// ---------------- zero + edge dtype detection (fused) ----------------
__global__ void zero_start(const int* ei32, int E, int n) {
    int i = blockIdx.x * blockDim.x + threadIdx.x;
    int stride = gridDim.x * blockDim.x;
    for (int j = i; j < n; j += stride) { g_cnt[j] = 0; g_fill[j] = 0; }
    if (i == 0) {
        int all0 = 1;
        for (int k = 0; k < 64; k++) {
            long long p = 1 + 2 * ((long long)k * (E / 2 - 1) / 64);
            if (ei32[p] != 0) { all0 = 0; break; }
        }
        g_is64 = all0;
    }
}

__device__ __forceinline__ int load_idx(const void* ei, int E, int half, int e, int is64, int n) {
    int v;
    if (is64) v = (int)((const long long*)ei)[(size_t)half * E + e];
    else      v = ((const int*)ei)[(size_t)half * E + e];
    return min(max(v, 0), n - 1);  // defensive clamp
}

__global__ void count_kernel(const void* __restrict__ ei, int E, int n) {
    int e = blockIdx.x * blockDim.x + threadIdx.x;
    if (e >= E) return;
    int is64 = g_is64;
    int d = load_idx(ei, E, 1, e, is64, n);
    atomicAdd(&g_cnt[d], 1);
}

// ---------------- 3-phase parallel exclusive scan ----------------
__global__ void __launch_bounds__(256) scan_partial(int n) {
    int t = threadIdx.x;
    int i = blockIdx.x * 256 + t;
    int v = (i < n) ? g_cnt[i] : 0;
    int w = v;
#pragma unroll
    for (int off = 16; off >= 1; off >>= 1) w += __shfl_xor_sync(0xffffffffu, w, off);
    __shared__ int red[8];
    if ((t & 31) == 0) red[t >> 5] = w;
    __syncthreads();
    if (t == 0) {
        int s = 0;
#pragma unroll
        for (int k = 0; k < 8; k++) s += red[k];
        g_bsum[blockIdx.x] = s;
    }
}

__global__ void __launch_bounds__(256) scan_bsum(int nb, int n) {
    __shared__ int s[256];
    int t = threadIdx.x;
    int v = (t < nb) ? g_bsum[t] : 0;
    s[t] = v;
    __syncthreads();
#pragma unroll
    for (int off = 1; off < 256; off <<= 1) {
        int a = s[t];
        int b = (t >= off) ? s[t - off] : 0;
        __syncthreads();
        s[t] = a + b;
        __syncthreads();
    }
    if (t < nb) g_bscan[t] = s[t] - v;
    if (t == nb - 1) g_rowptr[n] = s[t];
}

__global__ void __launch_bounds__(256) scan_final(int n) {
    int t = threadIdx.x;
    int lane = t & 31;
    int wid = t >> 5;
    int i = blockIdx.x * 256 + t;
    int v = (i < n) ? g_cnt[i] : 0;
    int inc = v;
#pragma unroll
    for (int off = 1; off < 32; off <<= 1) {
        int u = __shfl_up_sync(0xffffffffu, inc, off);
        if (lane >= off) inc += u;
    }
    __shared__ int wsum[8];
    if (lane == 31) wsum[wid] = inc;
    __syncthreads();
    if (t == 0) {
        int s = 0;
#pragma unroll
        for (int k = 0; k < 8; k++) { int u = wsum[k]; wsum[k] = s; s += u; }
    }
    __syncthreads();
    if (i < n) g_rowptr[i] = g_bscan[blockIdx.x] + wsum[wid] + inc - v;
}

__global__ void fill_kernel(const void* __restrict__ ei, int E, int n) {
    int e = blockIdx.x * blockDim.x + threadIdx.x;
    if (e >= E) return;
    int is64 = g_is64;
    int s = load_idx(ei, E, 0, e, is64, n);
    int d = load_idx(ei, E, 1, e, is64, n);
    int pos = g_rowptr[d] + atomicAdd(&g_fill[d], 1);
    if (pos < EMAX) g_csr_src[pos] = s;
}

// ---------------- Fused layer: CIN=64 (dynamic smem, ROWS=64) ----------------
// Block: 256 threads (8 warps), 64 rows/block (8 nodes per warp).
// Phase 1: warp-per-node CSR gather (mean agg) + own h row -> shared
// Phase 2: GEMM  out = relu([agg|h] @ [Wl;Wr] + bl), 4 rows x 4 cols per thread
//          (each LDS.128 weight load feeds 16 FMA -> FMA-pipe bound)
// FT: fuse t = out @ Wl4 (scalar per node) via 16-lane butterfly.
#define F64_ROWS 64
#define F64_L 132
#define F64_DSMEM (2 * 64 * 64 * 4 + F64_ROWS * F64_L * 4 + 64 * 4 + 64 * 4)

template <bool FT>
__global__ void __launch_bounds__(256) fused64(
    int in_idx, int out_idx,
    const float* __restrict__ Wl, const float* __restrict__ bl,
    const float* __restrict__ Wr, const float* __restrict__ Wl4,
    int n)
{
    extern __shared__ __align__(16) float dyn[];
    float* w_s   = dyn;                         // 2*64*64
    float* in_s  = w_s + 2 * 64 * 64;           // ROWS * L
    float* bl_s  = in_s + F64_ROWS * F64_L;     // 64
    float* wl4_s = bl_s + 64;                   // 64

    const float* hin = g_h[in_idx];
    float* hout = g_h[out_idx];

    int tid = threadIdx.x;
    int base = blockIdx.x * F64_ROWS;
    int warp = tid >> 5;
    int lane = tid & 31;

    for (int i = tid; i < 64 * 64; i += 256) {
        w_s[i] = Wl[i];
        w_s[64 * 64 + i] = Wr[i];
    }
    if (tid < 64) {
        bl_s[tid] = bl[tid];
        if (FT) wl4_s[tid] = Wl4[tid];
    }

    // Phase 1: gather (warp-uniform control per row)
#pragma unroll
    for (int q = 0; q < 8; q++) {
        int r = warp * 8 + q;
        int row = base + r;
        float2 acc = make_float2(0.f, 0.f);
        if (row < n) {
            int start = g_rowptr[row];
            int end = g_rowptr[row + 1];
            for (int j = start; j < end; j += 32) {
                int m = min(32, end - j);
                int eid = (lane < m) ? g_csr_src[j + lane] : 0;
#pragma unroll
                for (int k = 0; k < 32; k += 8) {
                    if (k >= m) break;
                    float2 v[8];
#pragma unroll
                    for (int u = 0; u < 8; u++) {
                        int s = __shfl_sync(0xffffffffu, eid, k + u);
                        if (k + u < m)
                            v[u] = *(const float2*)(hin + (size_t)s * 64 + 2 * lane);
                        else
                            v[u] = make_float2(0.f, 0.f);
                    }
#pragma unroll
                    for (int u = 0; u < 8; u++) { acc.x += v[u].x; acc.y += v[u].y; }
                }
            }
            int deg = end - start;
            float inv = 1.0f / (float)max(deg, 1);
            acc.x *= inv; acc.y *= inv;
            float2 hv = *(const float2*)(hin + (size_t)row * 64 + 2 * lane);
            *(float2*)&in_s[r * F64_L + 66 + 2 * lane] = hv;
        }
        *(float2*)&in_s[r * F64_L + 2 * lane] = acc;
    }
    __syncthreads();

    // Phase 2: GEMM. thread -> (rr, cg): rows rr+{0,16,32,48}, cols [cg*4, cg*4+4)
    int rr = tid >> 4;
    int cg = tid & 15;
    int j0 = cg * 4;
    const float4* w4 = (const float4*)w_s;

    float a[4][4];
#pragma unroll
    for (int rq = 0; rq < 4; rq++)
#pragma unroll
        for (int c = 0; c < 4; c++) a[rq][c] = bl_s[j0 + c];

    const float* rp[4];
#pragma unroll
    for (int rq = 0; rq < 4; rq++) rp[rq] = &in_s[(rr + rq * 16) * F64_L];

#pragma unroll
    for (int k = 0; k < 64; k++) {
        float4 w = w4[k * 16 + cg];
#pragma unroll
        for (int rq = 0; rq < 4; rq++) {
            float x = rp[rq][k];
            a[rq][0] += x * w.x; a[rq][1] += x * w.y; a[rq][2] += x * w.z; a[rq][3] += x * w.w;
        }
    }
#pragma unroll
    for (int k = 0; k < 64; k++) {
        float4 w = w4[(64 + k) * 16 + cg];
#pragma unroll
        for (int rq = 0; rq < 4; rq++) {
            float x = rp[rq][66 + k];
            a[rq][0] += x * w.x; a[rq][1] += x * w.y; a[rq][2] += x * w.z; a[rq][3] += x * w.w;
        }
    }

#pragma unroll
    for (int rq = 0; rq < 4; rq++) {
#pragma unroll
        for (int c = 0; c < 4; c++) a[rq][c] = fmaxf(a[rq][c], 0.f);
        int row = base + rr + rq * 16;
        if (row < n)
            *(float4*)(hout + (size_t)row * 64 + j0) = make_float4(a[rq][0], a[rq][1], a[rq][2], a[rq][3]);
    }

    if (FT) {
#pragma unroll
        for (int rq = 0; rq < 4; rq++) {
            float p = a[rq][0] * wl4_s[j0] + a[rq][1] * wl4_s[j0 + 1]
                    + a[rq][2] * wl4_s[j0 + 2] + a[rq][3] * wl4_s[j0 + 3];
#pragma unroll
            for (int off = 8; off >= 1; off >>= 1)
                p += __shfl_xor_sync(0xffffffffu, p, off);
            int row = base + rr + rq * 16;
            if (cg == 0 && row < n) g_t[row] = p;
        }
    }
}

// ---------------- Fused layer 0: CIN=13 ----------------
__global__ void __launch_bounds__(256) fused13(
    const float* __restrict__ x,
    const float* __restrict__ Wl, const float* __restrict__ bl,
    const float* __restrict__ Wr, int n)
{
    constexpr int ROWS = 32;
    constexpr int L = 28;  // agg [0..12], pad, h [14..26]
    __shared__ __align__(16) float w_s[2 * 13 * 64];
    __shared__ __align__(16) float in_s[ROWS * L];
    __shared__ float bl_s[64];

    float* hout = g_h[0];
    int tid = threadIdx.x;
    int base = blockIdx.x * ROWS;
    int warp = tid >> 5;
    int lane = tid & 31;

    for (int i = tid; i < 2 * 13 * 64; i += 256) w_s[i] = (i < 13 * 64) ? Wl[i] : Wr[i - 13 * 64];
    if (tid < 64) bl_s[tid] = bl[tid];

    for (int q = 0; q < 4; q++) {
        int r = warp * 4 + q;
        int row = base + r;
        float acc = 0.f;
        if (row < n) {
            int start = g_rowptr[row];
            int end = g_rowptr[row + 1];
            for (int j = start; j < end; j += 32) {
                int m = min(32, end - j);
                int eid = (lane < m) ? g_csr_src[j + lane] : 0;
#pragma unroll
                for (int k = 0; k < 32; k += 8) {
                    if (k >= m) break;
                    float v[8];
#pragma unroll
                    for (int u = 0; u < 8; u++) {
                        int s = __shfl_sync(0xffffffffu, eid, k + u);
                        v[u] = (lane < 13 && k + u < m) ? __ldg(&x[(size_t)s * 13 + lane]) : 0.f;
                    }
#pragma unroll
                    for (int u = 0; u < 8; u++) acc += v[u];
                }
            }
            int deg = end - start;
            float inv = 1.0f / (float)max(deg, 1);
            if (lane < 13) {
                in_s[r * L + lane] = acc * inv;
                in_s[r * L + 14 + lane] = __ldg(&x[(size_t)row * 13 + lane]);
            }
        } else if (lane < 13) {
            in_s[r * L + lane] = 0.f;
            in_s[r * L + 14 + lane] = 0.f;
        }
    }
    __syncthreads();

    int rr = tid >> 4;
    int cg = tid & 15;
    int j0 = cg * 4;
    const float4* w4 = (const float4*)w_s;

    float a0[4], a1[4];
#pragma unroll
    for (int c = 0; c < 4; c++) { a0[c] = bl_s[j0 + c]; a1[c] = bl_s[j0 + c]; }

    const float* r0p = &in_s[rr * L];
    const float* r1p = &in_s[(rr + 16) * L];
#pragma unroll
    for (int k = 0; k < 13; k++) {
        float4 w = w4[k * 16 + cg];
        float x0 = r0p[k], x1 = r1p[k];
        a0[0] += x0 * w.x; a0[1] += x0 * w.y; a0[2] += x0 * w.z; a0[3] += x0 * w.w;
        a1[0] += x1 * w.x; a1[1] += x1 * w.y; a1[2] += x1 * w.z; a1[3] += x1 * w.w;
    }
#pragma unroll
    for (int k = 0; k < 13; k++) {
        float4 w = w4[(13 + k) * 16 + cg];
        float x0 = r0p[14 + k], x1 = r1p[14 + k];
        a0[0] += x0 * w.x; a0[1] += x0 * w.y; a0[2] += x0 * w.z; a0[3] += x0 * w.w;
        a1[0] += x1 * w.x; a1[1] += x1 * w.y; a1[2] += x1 * w.z; a1[3] += x1 * w.w;
    }

    int row0 = base + rr;
    int row1 = base + rr + 16;
    if (row0 < n) {
#pragma unroll
        for (int c = 0; c < 4; c++) a0[c] = fmaxf(a0[c], 0.f);
        *(float4*)(hout + (size_t)row0 * 64 + j0) = make_float4(a0[0], a0[1], a0[2], a0[3]);
    }
    if (row1 < n) {
#pragma unroll
        for (int c = 0; c < 4; c++) a1[c] = fmaxf(a1[c], 0.f);
        *(float4*)(hout + (size_t)row1 * 64 + j0) = make_float4(a1[0], a1[1], a1[2], a1[3]);
    }
}

// ---------------- Final layer (64 -> 1), gather of precomputed t ----------------
__global__ void __launch_bounds__(256) final_kernel(
    int in_idx,
    const float* __restrict__ Wr,
    const float* __restrict__ bl,
    float* __restrict__ out, int n)
{
    __shared__ float w[64];
    if (threadIdx.x < 64) w[threadIdx.x] = Wr[threadIdx.x];
    __syncthreads();
    const float* h = g_h[in_idx];

    int gw = (blockIdx.x * blockDim.x + threadIdx.x) >> 5;
    if (gw >= n) return;
    int lane = threadIdx.x & 31;

    int start = g_rowptr[gw];
    int end = g_rowptr[gw + 1];
    float sum = 0.f;
    for (int j = start + lane; j < end; j += 32) sum += __ldg(&g_t[g_csr_src[j]]);

    float inv = 1.0f / (float)max(end - start, 1);
    float2 hv = *(const float2*)(h + (size_t)gw * 64 + 2 * lane);
    float2 wv = *(const float2*)&w[2 * lane];
    float v = sum * inv + hv.x * wv.x + hv.y * wv.y;
#pragma unroll
    for (int off = 16; off >= 1; off >>= 1) v += __shfl_xor_sync(0xffffffffu, v, off);

    if (lane == 0) {
        float z = v + bl[0];
        out[gw] = 1.0f / (1.0f + __expf(-z));
    }
}

// ---------------- launch ----------------
extern "C" void kernel_launch(void* const* d_in, const int* in_sizes, int n_in,
                              void* d_out, int out_size) {
    const float* x = (const float*)d_in[0];
    const void* ei = d_in[1];
    const float* Wl[5]; const float* bl[5]; const float* Wr[5];
    for (int i = 0; i < 5; i++) {
        Wl[i] = (const float*)d_in[2 + 3 * i];
        bl[i] = (const float*)d_in[3 + 3 * i];
        Wr[i] = (const float*)d_in[4 + 3 * i];
    }
    int n = in_sizes[0] / 13;
    int E = in_sizes[1] / 2;
    float* out = (float*)d_out;

    int eb = (E + 255) / 256;
    int nb = (n + 255) / 256;
    int fb13 = (n + 31) / 32;
    int fb64 = (n + F64_ROWS - 1) / F64_ROWS;

    cudaFuncSetAttribute(fused64<false>, cudaFuncAttributeMaxDynamicSharedMemorySize, F64_DSMEM);
    cudaFuncSetAttribute(fused64<true>,  cudaFuncAttributeMaxDynamicSharedMemorySize, F64_DSMEM);

    zero_start<<<64, 256>>>((const int*)ei, E, n);
    count_kernel<<<eb, 256>>>(ei, E, n);
    scan_partial<<<nb, 256>>>(n);
    scan_bsum<<<1, 256>>>(nb, n);
    scan_final<<<nb, 256>>>(n);
    fill_kernel<<<eb, 256>>>(ei, E, n);

    fused13<<<fb13, 256>>>(x, Wl[0], bl[0], Wr[0], n);                                  // -> g_h[0]
    fused64<false><<<fb64, 256, F64_DSMEM>>>(0, 1, Wl[1], bl[1], Wr[1], Wl[1], n);      // h0 -> h1
    fused64<false><<<fb64, 256, F64_DSMEM>>>(1, 0, Wl[2], bl[2], Wr[2], Wl[2], n);      // h1 -> h0
    fused64<true><<<fb64, 256, F64_DSMEM>>>(0, 1, Wl[3], bl[3], Wr[3], Wl[4], n);       // h0 -> h1, t = h3 @ Wl4
    final_kernel<<<(n * 32 + 255) / 256, 256>>>(1, Wr[4], bl[4], out, n);
}